// round 7
// baseline (speedup 1.0000x reference)
#include <cuda_runtime.h>
#include <math.h>
#include <stdint.h>

#define BN_ 8
#define L_ 2048
#define D_ 1024

// Scratch
__device__ float g_E[(size_t)BN_ * L_ * L_];
__device__ float g_rmax[BN_ * L_];
__device__ float g_rsumInv[BN_ * L_];
__device__ float g_cmax[BN_ * L_];
__device__ float g_csumInv[BN_ * L_];

#define NEG_INF __int_as_float(0xff800000)

static __device__ __forceinline__ uint32_t cvt_tf32(float x) {
    uint32_t h;
    asm("cvt.rna.tf32.f32 %0, %1;" : "=r"(h) : "f"(x));
    return h;
}
static __device__ __forceinline__ void split2(float x, float& h, float& l) {
    h = __uint_as_float(cvt_tf32(x));
    l = x - h;
}
static __device__ __forceinline__ void mma8(float c[4], const uint32_t a[4],
                                            const uint32_t b[2]) {
    asm volatile(
        "mma.sync.aligned.m16n8k8.row.col.f32.tf32.tf32.f32 "
        "{%0,%1,%2,%3},{%4,%5,%6,%7},{%8,%9},{%0,%1,%2,%3};"
        : "+f"(c[0]), "+f"(c[1]), "+f"(c[2]), "+f"(c[3])
        : "r"(a[0]), "r"(a[1]), "r"(a[2]), "r"(a[3]), "r"(b[0]), "r"(b[1]));
}

// ---------------------------------------------------------------------------
// E = A @ B^T via 3xTF32. 128x128 tile, BK=32, 16 warps (4m x 4n), 512 thr.
// ---------------------------------------------------------------------------
#define EPAD 36
#define EBUF (128 * EPAD)
__global__ __launch_bounds__(512, 1) void k_gemm_e(const float* __restrict__ A,
                                                   const float* __restrict__ B) {
    extern __shared__ float sm[];
    float* tAH = sm;                 // 2 * EBUF
    float* tAL = sm + 2 * EBUF;
    float* tBH = sm + 4 * EBUF;
    float* tBL = sm + 6 * EBUF;
    const int tid = threadIdx.x, lane = tid & 31, wid = tid >> 5;
    const int wm = wid & 3, wn = wid >> 2;           // 4 x 4
    const int q = lane >> 2, r = lane & 3;
    const int b = blockIdx.z, i0 = blockIdx.y * 128, j0 = blockIdx.x * 128;
    const float* Ab = A + ((size_t)b * L_ + i0) * D_;
    const float* Bb = B + ((size_t)b * L_ + j0) * D_;

    float acc[2][4][4];
    #pragma unroll
    for (int mt = 0; mt < 2; mt++)
        #pragma unroll
        for (int nt = 0; nt < 4; nt++)
            #pragma unroll
            for (int e = 0; e < 4; e++) acc[mt][nt][e] = 0.f;

    const int srow = tid >> 3;            // 0..63
    const int sch = tid & 7;              // k-quad 0..7

    float4 ar[2], br[2];
    #define LOADREGS_E(c)                                                        \
        do {                                                                     \
            const int _k0 = (c) * 32;                                            \
            _Pragma("unroll")                                                    \
            for (int t = 0; t < 2; t++) {                                        \
                int row = t * 64 + srow;                                         \
                ar[t] = *(const float4*)(Ab + (size_t)row * D_ + _k0 + sch * 4); \
                br[t] = *(const float4*)(Bb + (size_t)row * D_ + _k0 + sch * 4); \
            }                                                                    \
        } while (0)
    #define STAGE_E(bufn)                                                        \
        do {                                                                     \
            _Pragma("unroll")                                                    \
            for (int t = 0; t < 2; t++) {                                        \
                int row = t * 64 + srow;                                         \
                int off = (bufn) * EBUF + row * EPAD + sch * 4;                  \
                float4 h, l;                                                     \
                split2(ar[t].x, h.x, l.x); split2(ar[t].y, h.y, l.y);            \
                split2(ar[t].z, h.z, l.z); split2(ar[t].w, h.w, l.w);            \
                *(float4*)(tAH + off) = h; *(float4*)(tAL + off) = l;            \
                split2(br[t].x, h.x, l.x); split2(br[t].y, h.y, l.y);            \
                split2(br[t].z, h.z, l.z); split2(br[t].w, h.w, l.w);            \
                *(float4*)(tBH + off) = h; *(float4*)(tBL + off) = l;            \
            }                                                                    \
        } while (0)

    LOADREGS_E(0);
    STAGE_E(0);
    LOADREGS_E(1);
    __syncthreads();   // buf0 ready

    for (int c = 0; c < 32; c++) {
        const int buf = c & 1;
        if (c + 1 < 32) {
            STAGE_E(buf ^ 1);
            if (c + 2 < 32) LOADREGS_E(c + 2);
        }
        const float* AH_ = tAH + buf * EBUF;
        const float* AL_ = tAL + buf * EBUF;
        const float* BH_ = tBH + buf * EBUF;
        const float* BL_ = tBL + buf * EBUF;
        #pragma unroll
        for (int ks = 0; ks < 4; ks++) {
            const int kb = ks * 8;
            uint32_t ah[2][4], al[2][4], bh[4][2], bl[4][2];
            #pragma unroll
            for (int mt = 0; mt < 2; mt++) {
                const int rb = wm * 32 + mt * 16;
                ah[mt][0] = __float_as_uint(AH_[(rb + q) * EPAD + kb + r]);
                ah[mt][1] = __float_as_uint(AH_[(rb + q + 8) * EPAD + kb + r]);
                ah[mt][2] = __float_as_uint(AH_[(rb + q) * EPAD + kb + r + 4]);
                ah[mt][3] = __float_as_uint(AH_[(rb + q + 8) * EPAD + kb + r + 4]);
                al[mt][0] = __float_as_uint(AL_[(rb + q) * EPAD + kb + r]);
                al[mt][1] = __float_as_uint(AL_[(rb + q + 8) * EPAD + kb + r]);
                al[mt][2] = __float_as_uint(AL_[(rb + q) * EPAD + kb + r + 4]);
                al[mt][3] = __float_as_uint(AL_[(rb + q + 8) * EPAD + kb + r + 4]);
            }
            #pragma unroll
            for (int nt = 0; nt < 4; nt++) {
                const int nb = wn * 32 + nt * 8;
                bh[nt][0] = __float_as_uint(BH_[(nb + q) * EPAD + kb + r]);
                bh[nt][1] = __float_as_uint(BH_[(nb + q) * EPAD + kb + r + 4]);
                bl[nt][0] = __float_as_uint(BL_[(nb + q) * EPAD + kb + r]);
                bl[nt][1] = __float_as_uint(BL_[(nb + q) * EPAD + kb + r + 4]);
            }
            #pragma unroll
            for (int mt = 0; mt < 2; mt++)
                #pragma unroll
                for (int nt = 0; nt < 4; nt++) {
                    mma8(acc[mt][nt], al[mt], bh[nt]);
                    mma8(acc[mt][nt], ah[mt], bl[nt]);
                    mma8(acc[mt][nt], ah[mt], bh[nt]);
                }
        }
        __syncthreads();
    }
    #undef STAGE_E
    #undef LOADREGS_E

    float* Eb = g_E + ((size_t)b * L_ + i0) * L_ + j0;
    #pragma unroll
    for (int mt = 0; mt < 2; mt++)
        #pragma unroll
        for (int nt = 0; nt < 4; nt++) {
            int row = wm * 32 + mt * 16 + q;
            int col = wn * 32 + nt * 8 + r * 2;
            *(float2*)(Eb + (size_t)row * L_ + col) =
                make_float2(acc[mt][nt][0], acc[mt][nt][1]);
            *(float2*)(Eb + (size_t)(row + 8) * L_ + col) =
                make_float2(acc[mt][nt][2], acc[mt][nt][3]);
        }
}

// ---------------------------------------------------------------------------
// Row / col softmax stats
// ---------------------------------------------------------------------------
__global__ __launch_bounds__(256) void k_rowstats() {
    const int b = blockIdx.y, rrow = blockIdx.x;
    const float* row = g_E + (size_t)(b * L_ + rrow) * L_;
    const int tid = threadIdx.x;
    __shared__ float red[256];

    float m = NEG_INF;
    for (int j = tid * 4; j < L_; j += 1024) {
        float4 v = *(const float4*)(row + j);
        m = fmaxf(m, fmaxf(fmaxf(v.x, v.y), fmaxf(v.z, v.w)));
    }
    red[tid] = m; __syncthreads();
    for (int s = 128; s >= 1; s >>= 1) {
        if (tid < s) red[tid] = fmaxf(red[tid], red[tid + s]);
        __syncthreads();
    }
    const float M = red[0];
    __syncthreads();

    float sum = 0.f;
    for (int j = tid * 4; j < L_; j += 1024) {
        float4 v = *(const float4*)(row + j);
        sum += __expf(v.x - M) + __expf(v.y - M) + __expf(v.z - M) + __expf(v.w - M);
    }
    red[tid] = sum; __syncthreads();
    for (int s = 128; s >= 1; s >>= 1) {
        if (tid < s) red[tid] += red[tid + s];
        __syncthreads();
    }
    if (tid == 0) {
        g_rmax[b * L_ + rrow] = M;
        g_rsumInv[b * L_ + rrow] = 1.0f / red[0];
    }
}

__global__ __launch_bounds__(256) void k_colstats() {
    const int b = blockIdx.y;
    const int jt = threadIdx.x & 31;
    const int isl = threadIdx.x >> 5;
    const int j = blockIdx.x * 32 + jt;
    const float* base = g_E + (size_t)b * L_ * L_ + j;

    float m = NEG_INF, s = 0.f;
    const int ibeg = isl * 256, iend = ibeg + 256;
    for (int i = ibeg; i < iend; i++) {
        float x = base[(size_t)i * L_];
        if (x <= m) {
            s += __expf(x - m);
        } else {
            s = s * __expf(m - x) + 1.f;
            m = x;
        }
    }
    __shared__ float ms[8][32], ss[8][32];
    ms[isl][jt] = m; ss[isl][jt] = s;
    __syncthreads();
    if (isl == 0) {
        float M = m, S = s;
        #pragma unroll
        for (int k = 1; k < 8; k++) {
            float mk = ms[k][jt], sk = ss[k][jt];
            if (mk <= M) {
                S += sk * __expf(mk - M);
            } else {
                S = S * __expf(M - mk) + sk;
                M = mk;
            }
        }
        g_cmax[b * L_ + j] = M;
        g_csumInv[b * L_ + j] = 1.0f / S;
    }
}

// ---------------------------------------------------------------------------
// a_tilda[i,d] = sum_j P[i,j]*B[j,d].  16 warps (4m x 4n), 512 threads.
// ---------------------------------------------------------------------------
#define PPAD 36
#define PBUF (128 * PPAD)
#define KNPAD 136
#define KNBUF (32 * KNPAD)
__global__ __launch_bounds__(512, 1) void k_atilda(const float* __restrict__ B,
                                                   float* __restrict__ out) {
    extern __shared__ float sm[];
    float* Ps = sm;                              // 2 * PBUF
    float* BH = sm + 2 * PBUF;                   // 2 * KNBUF
    float* BL = sm + 2 * PBUF + 2 * KNBUF;       // 2 * KNBUF
    float* rm_s = sm + 2 * PBUF + 4 * KNBUF;
    float* ri_s = rm_s + 128;
    const int tid = threadIdx.x, lane = tid & 31, wid = tid >> 5;
    const int wm = wid & 3, wn = wid >> 2;
    const int q = lane >> 2, r = lane & 3;
    const int b = blockIdx.z, i0 = blockIdx.y * 128, d0 = blockIdx.x * 128;
    const float* Eb = g_E + (size_t)b * L_ * L_;
    const float* Bb = B + (size_t)b * L_ * D_;

    if (tid < 128) {
        rm_s[tid] = g_rmax[b * L_ + i0 + tid];
        ri_s[tid] = g_rsumInv[b * L_ + i0 + tid];
    }

    float acc[2][4][4];
    #pragma unroll
    for (int mt = 0; mt < 2; mt++)
        #pragma unroll
        for (int nt = 0; nt < 4; nt++)
            #pragma unroll
            for (int e = 0; e < 4; e++) acc[mt][nt][e] = 0.f;

    const int prow = tid >> 3, pch = tid & 7;        // P: 64-row groups x2
    const int brow = tid >> 5, bch = tid & 31;       // B: 16-row groups x2

    float4 pe[2], be[2];
    #define LOADREGS_P(c)                                                                     \
        do {                                                                                  \
            const int _j0 = (c) * 32;                                                         \
            _Pragma("unroll")                                                                 \
            for (int t = 0; t < 2; t++) {                                                     \
                pe[t] = *(const float4*)(Eb + (size_t)(i0 + t * 64 + prow) * L_ + _j0 + pch * 4); \
                be[t] = *(const float4*)(Bb + (size_t)(_j0 + t * 16 + brow) * D_ + d0 + bch * 4); \
            }                                                                                 \
        } while (0)
    #define STAGE_P(bufn)                                                                     \
        do {                                                                                  \
            float* P_ = Ps + (bufn) * PBUF;                                                   \
            float* BH_ = BH + (bufn) * KNBUF;                                                 \
            float* BL_ = BL + (bufn) * KNBUF;                                                 \
            _Pragma("unroll")                                                                 \
            for (int t = 0; t < 2; t++) {                                                     \
                int rp = t * 64 + prow;                                                       \
                float m = rm_s[rp], siv = ri_s[rp];                                           \
                float4 p;                                                                     \
                p.x = __uint_as_float(cvt_tf32(__expf(pe[t].x - m) * siv));                   \
                p.y = __uint_as_float(cvt_tf32(__expf(pe[t].y - m) * siv));                   \
                p.z = __uint_as_float(cvt_tf32(__expf(pe[t].z - m) * siv));                   \
                p.w = __uint_as_float(cvt_tf32(__expf(pe[t].w - m) * siv));                   \
                *(float4*)(P_ + rp * PPAD + pch * 4) = p;                                     \
                float4 h, l;                                                                  \
                split2(be[t].x, h.x, l.x); split2(be[t].y, h.y, l.y);                         \
                split2(be[t].z, h.z, l.z); split2(be[t].w, h.w, l.w);                         \
                int off = (t * 16 + brow) * KNPAD + bch * 4;                                  \
                *(float4*)(BH_ + off) = h;                                                    \
                *(float4*)(BL_ + off) = l;                                                    \
            }                                                                                 \
        } while (0)

    LOADREGS_P(0);
    __syncthreads();   // rm_s/ri_s ready
    STAGE_P(0);
    LOADREGS_P(1);
    __syncthreads();   // buf0 ready

    for (int c = 0; c < 64; c++) {
        const int buf = c & 1;
        if (c + 1 < 64) {
            STAGE_P(buf ^ 1);
            if (c + 2 < 64) LOADREGS_P(c + 2);
        }
        const float* P_ = Ps + buf * PBUF;
        const float* BH_ = BH + buf * KNBUF;
        const float* BL_ = BL + buf * KNBUF;
        #pragma unroll
        for (int ks = 0; ks < 4; ks++) {
            const int kb = ks * 8;
            uint32_t pa[2][4], bh[4][2], bl[4][2];
            #pragma unroll
            for (int mt = 0; mt < 2; mt++) {
                const int rb = wm * 32 + mt * 16;
                pa[mt][0] = __float_as_uint(P_[(rb + q) * PPAD + kb + r]);
                pa[mt][1] = __float_as_uint(P_[(rb + q + 8) * PPAD + kb + r]);
                pa[mt][2] = __float_as_uint(P_[(rb + q) * PPAD + kb + r + 4]);
                pa[mt][3] = __float_as_uint(P_[(rb + q + 8) * PPAD + kb + r + 4]);
            }
            #pragma unroll
            for (int nt = 0; nt < 4; nt++) {
                const int nb = wn * 32 + nt * 8;
                bh[nt][0] = __float_as_uint(BH_[(kb + r) * KNPAD + nb + q]);
                bh[nt][1] = __float_as_uint(BH_[(kb + r + 4) * KNPAD + nb + q]);
                bl[nt][0] = __float_as_uint(BL_[(kb + r) * KNPAD + nb + q]);
                bl[nt][1] = __float_as_uint(BL_[(kb + r + 4) * KNPAD + nb + q]);
            }
            #pragma unroll
            for (int mt = 0; mt < 2; mt++)
                #pragma unroll
                for (int nt = 0; nt < 4; nt++) {
                    mma8(acc[mt][nt], pa[mt], bl[nt]);
                    mma8(acc[mt][nt], pa[mt], bh[nt]);
                }
        }
        __syncthreads();
    }
    #undef STAGE_P
    #undef LOADREGS_P

    float* Ob = out + ((size_t)b * L_ + i0) * D_ + d0;
    #pragma unroll
    for (int mt = 0; mt < 2; mt++)
        #pragma unroll
        for (int nt = 0; nt < 4; nt++) {
            int row = wm * 32 + mt * 16 + q;
            int col = wn * 32 + nt * 8 + r * 2;
            *(float2*)(Ob + (size_t)row * D_ + col) =
                make_float2(acc[mt][nt][0], acc[mt][nt][1]);
            *(float2*)(Ob + (size_t)(row + 8) * D_ + col) =
                make_float2(acc[mt][nt][2], acc[mt][nt][3]);
        }
}

// ---------------------------------------------------------------------------
// b_tilda[j,d] = sum_i Q[i,j]*A[i,d].  16 warps (4m x 4n), 512 threads.
// ---------------------------------------------------------------------------
__global__ __launch_bounds__(512, 1) void k_btilda(const float* __restrict__ A,
                                                   float* __restrict__ out) {
    extern __shared__ float sm[];
    float* Qs = sm;                              // 2 * KNBUF
    float* AH = sm + 2 * KNBUF;                  // 2 * KNBUF
    float* AL = sm + 4 * KNBUF;                  // 2 * KNBUF
    float* cm_s = sm + 6 * KNBUF;
    float* ci_s = cm_s + 128;
    const int tid = threadIdx.x, lane = tid & 31, wid = tid >> 5;
    const int wm = wid & 3, wn = wid >> 2;
    const int q = lane >> 2, r = lane & 3;
    const int b = blockIdx.z, j0 = blockIdx.y * 128, d0 = blockIdx.x * 128;
    const float* Eb = g_E + (size_t)b * L_ * L_;
    const float* Ab = A + (size_t)b * L_ * D_;

    if (tid < 128) {
        cm_s[tid] = g_cmax[b * L_ + j0 + tid];
        ci_s[tid] = g_csumInv[b * L_ + j0 + tid];
    }

    float acc[2][4][4];
    #pragma unroll
    for (int mt = 0; mt < 2; mt++)
        #pragma unroll
        for (int nt = 0; nt < 4; nt++)
            #pragma unroll
            for (int e = 0; e < 4; e++) acc[mt][nt][e] = 0.f;

    const int srow = tid >> 5, sch = tid & 31;   // 16-row groups x2

    float4 qe[2], ae[2];
    #define LOADREGS_Q(c)                                                               \
        do {                                                                            \
            const int _i0 = (c) * 32;                                                   \
            _Pragma("unroll")                                                           \
            for (int t = 0; t < 2; t++) {                                               \
                int irow = _i0 + t * 16 + srow;                                         \
                qe[t] = *(const float4*)(Eb + (size_t)irow * L_ + j0 + sch * 4);        \
                ae[t] = *(const float4*)(Ab + (size_t)irow * D_ + d0 + sch * 4);        \
            }                                                                           \
        } while (0)
    #define STAGE_Q(bufn)                                                               \
        do {                                                                            \
            float* Q_ = Qs + (bufn) * KNBUF;                                            \
            float* AH_ = AH + (bufn) * KNBUF;                                           \
            float* AL_ = AL + (bufn) * KNBUF;                                           \
            _Pragma("unroll")                                                           \
            for (int t = 0; t < 2; t++) {                                               \
                int irow = t * 16 + srow;                                               \
                int jj = sch * 4;                                                       \
                float4 p;                                                               \
                p.x = __uint_as_float(cvt_tf32(__expf(qe[t].x - cm_s[jj]) * ci_s[jj])); \
                p.y = __uint_as_float(cvt_tf32(__expf(qe[t].y - cm_s[jj + 1]) * ci_s[jj + 1])); \
                p.z = __uint_as_float(cvt_tf32(__expf(qe[t].z - cm_s[jj + 2]) * ci_s[jj + 2])); \
                p.w = __uint_as_float(cvt_tf32(__expf(qe[t].w - cm_s[jj + 3]) * ci_s[jj + 3])); \
                *(float4*)(Q_ + irow * KNPAD + jj) = p;                                 \
                float4 h, l;                                                            \
                split2(ae[t].x, h.x, l.x); split2(ae[t].y, h.y, l.y);                   \
                split2(ae[t].z, h.z, l.z); split2(ae[t].w, h.w, l.w);                   \
                int off = irow * KNPAD + sch * 4;                                       \
                *(float4*)(AH_ + off) = h;                                              \
                *(float4*)(AL_ + off) = l;                                              \
            }                                                                           \
        } while (0)

    LOADREGS_Q(0);
    __syncthreads();   // cm_s/ci_s ready
    STAGE_Q(0);
    LOADREGS_Q(1);
    __syncthreads();   // buf0 ready

    for (int c = 0; c < 64; c++) {
        const int buf = c & 1;
        if (c + 1 < 64) {
            STAGE_Q(buf ^ 1);
            if (c + 2 < 64) LOADREGS_Q(c + 2);
        }
        const float* Q_ = Qs + buf * KNBUF;
        const float* AH_ = AH + buf * KNBUF;
        const float* AL_ = AL + buf * KNBUF;
        #pragma unroll
        for (int ks = 0; ks < 4; ks++) {
            const int kb = ks * 8;
            uint32_t qa[2][4], bh[4][2], bl[4][2];
            #pragma unroll
            for (int mt = 0; mt < 2; mt++) {
                const int mb = wm * 32 + mt * 16;
                qa[mt][0] = __float_as_uint(Q_[(kb + r) * KNPAD + mb + q]);
                qa[mt][1] = __float_as_uint(Q_[(kb + r) * KNPAD + mb + q + 8]);
                qa[mt][2] = __float_as_uint(Q_[(kb + r + 4) * KNPAD + mb + q]);
                qa[mt][3] = __float_as_uint(Q_[(kb + r + 4) * KNPAD + mb + q + 8]);
            }
            #pragma unroll
            for (int nt = 0; nt < 4; nt++) {
                const int nb = wn * 32 + nt * 8;
                bh[nt][0] = __float_as_uint(AH_[(kb + r) * KNPAD + nb + q]);
                bh[nt][1] = __float_as_uint(AH_[(kb + r + 4) * KNPAD + nb + q]);
                bl[nt][0] = __float_as_uint(AL_[(kb + r) * KNPAD + nb + q]);
                bl[nt][1] = __float_as_uint(AL_[(kb + r + 4) * KNPAD + nb + q]);
            }
            #pragma unroll
            for (int mt = 0; mt < 2; mt++)
                #pragma unroll
                for (int nt = 0; nt < 4; nt++) {
                    mma8(acc[mt][nt], qa[mt], bl[nt]);
                    mma8(acc[mt][nt], qa[mt], bh[nt]);
                }
        }
        __syncthreads();
    }
    #undef STAGE_Q
    #undef LOADREGS_Q

    float* Ob = out + ((size_t)b * L_ + j0) * D_ + d0;
    #pragma unroll
    for (int mt = 0; mt < 2; mt++)
        #pragma unroll
        for (int nt = 0; nt < 4; nt++) {
            int row = wm * 32 + mt * 16 + q;
            int col = wn * 32 + nt * 8 + r * 2;
            *(float2*)(Ob + (size_t)row * D_ + col) =
                make_float2(acc[mt][nt][0], acc[mt][nt][1]);
            *(float2*)(Ob + (size_t)(row + 8) * D_ + col) =
                make_float2(acc[mt][nt][2], acc[mt][nt][3]);
        }
}

// ---------------------------------------------------------------------------
extern "C" void kernel_launch(void* const* d_in, const int* in_sizes, int n_in,
                              void* d_out, int out_size) {
    const float* A = (const float*)d_in[0];
    const float* B = (const float*)d_in[1];
    float* out = (float*)d_out;
    float* a_tilda = out;
    float* b_tilda = out + (size_t)BN_ * L_ * D_;

    const int SMEM_E = 8 * EBUF * 4;                            // 147456 B
    const int SMEM_A = (2 * PBUF + 4 * KNBUF + 256) * 4;        // 107520 B
    const int SMEM_B = (6 * KNBUF + 256) * 4;                   // 105472 B
    cudaFuncSetAttribute(k_gemm_e, cudaFuncAttributeMaxDynamicSharedMemorySize, SMEM_E);
    cudaFuncSetAttribute(k_atilda, cudaFuncAttributeMaxDynamicSharedMemorySize, SMEM_A);
    cudaFuncSetAttribute(k_btilda, cudaFuncAttributeMaxDynamicSharedMemorySize, SMEM_B);

    k_gemm_e<<<dim3(L_ / 128, L_ / 128, BN_), 512, SMEM_E>>>(A, B);
    k_rowstats<<<dim3(L_, BN_), 256>>>();
    k_colstats<<<dim3(L_ / 32, BN_), 256>>>();
    k_atilda<<<dim3(D_ / 128, L_ / 128, BN_), 512, SMEM_A>>>(B, a_tilda);
    k_btilda<<<dim3(D_ / 128, L_ / 128, BN_), 512, SMEM_B>>>(A, b_tilda);
}

// round 8
// speedup vs baseline: 1.3062x; 1.3062x over previous
#include <cuda_runtime.h>
#include <math.h>
#include <stdint.h>

#define BN_ 8
#define L_ 2048
#define D_ 1024

// Scratch
__device__ float g_E[(size_t)BN_ * L_ * L_];
__device__ float g_rmax[BN_ * L_];
__device__ float g_rsumInv[BN_ * L_];
__device__ float g_cmax[BN_ * L_];
__device__ float g_csumInv[BN_ * L_];

#define NEG_INF __int_as_float(0xff800000)

static __device__ __forceinline__ uint32_t cvt_tf32(float x) {
    uint32_t h;
    asm("cvt.rna.tf32.f32 %0, %1;" : "=r"(h) : "f"(x));
    return h;
}
static __device__ __forceinline__ void split2(float x, float& h, float& l) {
    h = __uint_as_float(cvt_tf32(x));
    l = x - h;
}
static __device__ __forceinline__ void mma8(float c[4], const uint32_t a[4],
                                            const uint32_t b[2]) {
    asm volatile(
        "mma.sync.aligned.m16n8k8.row.col.f32.tf32.tf32.f32 "
        "{%0,%1,%2,%3},{%4,%5,%6,%7},{%8,%9},{%0,%1,%2,%3};"
        : "+f"(c[0]), "+f"(c[1]), "+f"(c[2]), "+f"(c[3])
        : "r"(a[0]), "r"(a[1]), "r"(a[2]), "r"(a[3]), "r"(b[0]), "r"(b[1]));
}

// ---------------------------------------------------------------------------
// E = A @ B^T via 3xTF32. 128x128 tile, BK=32, 8 warps (4m x 2n), 256 thr.
// Stage (split in regs) -> sync -> MMA -> sync, double buffered w/ LDG prefetch.
// ---------------------------------------------------------------------------
#define EPAD 36
#define EBUF (128 * EPAD)
__global__ __launch_bounds__(256, 1) void k_gemm_e(const float* __restrict__ A,
                                                   const float* __restrict__ B) {
    extern __shared__ float sm[];
    float* tAH = sm;                 // 2 * EBUF
    float* tAL = sm + 2 * EBUF;
    float* tBH = sm + 4 * EBUF;
    float* tBL = sm + 6 * EBUF;
    const int tid = threadIdx.x, lane = tid & 31, wid = tid >> 5;
    const int wm = wid & 3, wn = wid >> 2;
    const int q = lane >> 2, r = lane & 3;
    const int b = blockIdx.z, i0 = blockIdx.y * 128, j0 = blockIdx.x * 128;
    const float* Ab = A + ((size_t)b * L_ + i0) * D_;
    const float* Bb = B + ((size_t)b * L_ + j0) * D_;

    float acc[2][8][4];
    #pragma unroll
    for (int mt = 0; mt < 2; mt++)
        #pragma unroll
        for (int nt = 0; nt < 8; nt++)
            #pragma unroll
            for (int e = 0; e < 4; e++) acc[mt][nt][e] = 0.f;

    const int srow = tid >> 3;            // 0..31
    const int sch = tid & 7;              // k-quad 0..7

    float4 ar[4], br[4];
    #pragma unroll
    for (int t = 0; t < 4; t++) {
        int row = t * 32 + srow;
        ar[t] = *(const float4*)(Ab + (size_t)row * D_ + sch * 4);
        br[t] = *(const float4*)(Bb + (size_t)row * D_ + sch * 4);
    }

    for (int c = 0; c < 32; c++) {
        const int buf = c & 1;
        #pragma unroll
        for (int t = 0; t < 4; t++) {
            int row = t * 32 + srow;
            int off = buf * EBUF + row * EPAD + sch * 4;
            float4 h, l;
            split2(ar[t].x, h.x, l.x); split2(ar[t].y, h.y, l.y);
            split2(ar[t].z, h.z, l.z); split2(ar[t].w, h.w, l.w);
            *(float4*)(tAH + off) = h; *(float4*)(tAL + off) = l;
            split2(br[t].x, h.x, l.x); split2(br[t].y, h.y, l.y);
            split2(br[t].z, h.z, l.z); split2(br[t].w, h.w, l.w);
            *(float4*)(tBH + off) = h; *(float4*)(tBL + off) = l;
        }
        if (c + 1 < 32) {
            const int k0 = (c + 1) * 32;
            #pragma unroll
            for (int t = 0; t < 4; t++) {
                int row = t * 32 + srow;
                ar[t] = *(const float4*)(Ab + (size_t)row * D_ + k0 + sch * 4);
                br[t] = *(const float4*)(Bb + (size_t)row * D_ + k0 + sch * 4);
            }
        }
        __syncthreads();
        const float* AH_ = tAH + buf * EBUF;
        const float* AL_ = tAL + buf * EBUF;
        const float* BH_ = tBH + buf * EBUF;
        const float* BL_ = tBL + buf * EBUF;
        #pragma unroll
        for (int ks = 0; ks < 4; ks++) {
            const int kb = ks * 8;
            uint32_t ah[2][4], al[2][4], bh[8][2], bl[8][2];
            #pragma unroll
            for (int mt = 0; mt < 2; mt++) {
                const int rb = wm * 32 + mt * 16;
                ah[mt][0] = __float_as_uint(AH_[(rb + q) * EPAD + kb + r]);
                ah[mt][1] = __float_as_uint(AH_[(rb + q + 8) * EPAD + kb + r]);
                ah[mt][2] = __float_as_uint(AH_[(rb + q) * EPAD + kb + r + 4]);
                ah[mt][3] = __float_as_uint(AH_[(rb + q + 8) * EPAD + kb + r + 4]);
                al[mt][0] = __float_as_uint(AL_[(rb + q) * EPAD + kb + r]);
                al[mt][1] = __float_as_uint(AL_[(rb + q + 8) * EPAD + kb + r]);
                al[mt][2] = __float_as_uint(AL_[(rb + q) * EPAD + kb + r + 4]);
                al[mt][3] = __float_as_uint(AL_[(rb + q + 8) * EPAD + kb + r + 4]);
            }
            #pragma unroll
            for (int nt = 0; nt < 8; nt++) {
                const int nb = wn * 64 + nt * 8;
                bh[nt][0] = __float_as_uint(BH_[(nb + q) * EPAD + kb + r]);
                bh[nt][1] = __float_as_uint(BH_[(nb + q) * EPAD + kb + r + 4]);
                bl[nt][0] = __float_as_uint(BL_[(nb + q) * EPAD + kb + r]);
                bl[nt][1] = __float_as_uint(BL_[(nb + q) * EPAD + kb + r + 4]);
            }
            #pragma unroll
            for (int mt = 0; mt < 2; mt++)
                #pragma unroll
                for (int nt = 0; nt < 8; nt++) {
                    mma8(acc[mt][nt], al[mt], bh[nt]);
                    mma8(acc[mt][nt], ah[mt], bl[nt]);
                    mma8(acc[mt][nt], ah[mt], bh[nt]);
                }
        }
        __syncthreads();
    }

    float* Eb = g_E + ((size_t)b * L_ + i0) * L_ + j0;
    #pragma unroll
    for (int mt = 0; mt < 2; mt++)
        #pragma unroll
        for (int nt = 0; nt < 8; nt++) {
            int row = wm * 32 + mt * 16 + q;
            int col = wn * 64 + nt * 8 + r * 2;
            *(float2*)(Eb + (size_t)row * L_ + col) =
                make_float2(acc[mt][nt][0], acc[mt][nt][1]);
            *(float2*)(Eb + (size_t)(row + 8) * L_ + col) =
                make_float2(acc[mt][nt][2], acc[mt][nt][3]);
        }
}

// ---------------------------------------------------------------------------
// Row / col softmax stats
// ---------------------------------------------------------------------------
__global__ __launch_bounds__(256) void k_rowstats() {
    const int b = blockIdx.y, rrow = blockIdx.x;
    const float* row = g_E + (size_t)(b * L_ + rrow) * L_;
    const int tid = threadIdx.x;
    __shared__ float red[256];

    float m = NEG_INF;
    for (int j = tid * 4; j < L_; j += 1024) {
        float4 v = *(const float4*)(row + j);
        m = fmaxf(m, fmaxf(fmaxf(v.x, v.y), fmaxf(v.z, v.w)));
    }
    red[tid] = m; __syncthreads();
    for (int s = 128; s >= 1; s >>= 1) {
        if (tid < s) red[tid] = fmaxf(red[tid], red[tid + s]);
        __syncthreads();
    }
    const float M = red[0];
    __syncthreads();

    float sum = 0.f;
    for (int j = tid * 4; j < L_; j += 1024) {
        float4 v = *(const float4*)(row + j);
        sum += __expf(v.x - M) + __expf(v.y - M) + __expf(v.z - M) + __expf(v.w - M);
    }
    red[tid] = sum; __syncthreads();
    for (int s = 128; s >= 1; s >>= 1) {
        if (tid < s) red[tid] += red[tid + s];
        __syncthreads();
    }
    if (tid == 0) {
        g_rmax[b * L_ + rrow] = M;
        g_rsumInv[b * L_ + rrow] = 1.0f / red[0];
    }
}

__global__ __launch_bounds__(256) void k_colstats() {
    const int b = blockIdx.y;
    const int jt = threadIdx.x & 31;
    const int isl = threadIdx.x >> 5;
    const int j = blockIdx.x * 32 + jt;
    const float* base = g_E + (size_t)b * L_ * L_ + j;

    float m = NEG_INF, s = 0.f;
    const int ibeg = isl * 256, iend = ibeg + 256;
    for (int i = ibeg; i < iend; i++) {
        float x = base[(size_t)i * L_];
        if (x <= m) {
            s += __expf(x - m);
        } else {
            s = s * __expf(m - x) + 1.f;
            m = x;
        }
    }
    __shared__ float ms[8][32], ss[8][32];
    ms[isl][jt] = m; ss[isl][jt] = s;
    __syncthreads();
    if (isl == 0) {
        float M = m, S = s;
        #pragma unroll
        for (int k = 1; k < 8; k++) {
            float mk = ms[k][jt], sk = ss[k][jt];
            if (mk <= M) {
                S += sk * __expf(mk - M);
            } else {
                S = S * __expf(M - mk) + sk;
                M = mk;
            }
        }
        g_cmax[b * L_ + j] = M;
        g_csumInv[b * L_ + j] = 1.0f / S;
    }
}

// ---------------------------------------------------------------------------
// a_tilda[i,d] = sum_j P[i,j]*B[j,d].  P tf32 (exp), B single tf32 (no lo).
// Ps [m=i][k=j] pad 36; BH [k=j][n=d] pad 136.  8 warps (4m x 2n), 256 thr.
// ---------------------------------------------------------------------------
#define PPAD 36
#define PBUF (128 * PPAD)
#define KNPAD 136
#define KNBUF (32 * KNPAD)
__global__ __launch_bounds__(256, 1) void k_atilda(const float* __restrict__ B,
                                                   float* __restrict__ out) {
    extern __shared__ float sm[];
    float* Ps = sm;                              // 2 * PBUF
    float* BH = sm + 2 * PBUF;                   // 2 * KNBUF
    float* rm_s = sm + 2 * PBUF + 2 * KNBUF;
    float* ri_s = rm_s + 128;
    const int tid = threadIdx.x, lane = tid & 31, wid = tid >> 5;
    const int wm = wid & 3, wn = wid >> 2;
    const int q = lane >> 2, r = lane & 3;
    const int b = blockIdx.z, i0 = blockIdx.y * 128, d0 = blockIdx.x * 128;
    const float* Eb = g_E + (size_t)b * L_ * L_;
    const float* Bb = B + (size_t)b * L_ * D_;

    if (tid < 128) {
        rm_s[tid] = g_rmax[b * L_ + i0 + tid];
        ri_s[tid] = g_rsumInv[b * L_ + i0 + tid];
    }

    float acc[2][8][4];
    #pragma unroll
    for (int mt = 0; mt < 2; mt++)
        #pragma unroll
        for (int nt = 0; nt < 8; nt++)
            #pragma unroll
            for (int e = 0; e < 4; e++) acc[mt][nt][e] = 0.f;

    const int prow = tid >> 3, pch = tid & 7;        // P: 32-row groups
    const int brow = tid >> 5, bch = tid & 31;       // B: 8-row groups

    float4 pe[4], be[4];
    #pragma unroll
    for (int t = 0; t < 4; t++) {
        pe[t] = *(const float4*)(Eb + (size_t)(i0 + t * 32 + prow) * L_ + pch * 4);
        be[t] = *(const float4*)(Bb + (size_t)(t * 8 + brow) * D_ + d0 + bch * 4);
    }
    __syncthreads();   // rm_s/ri_s visible

    for (int c = 0; c < 64; c++) {
        const int buf = c & 1;
        float* P_ = Ps + buf * PBUF;
        float* BH_ = BH + buf * KNBUF;
        #pragma unroll
        for (int t = 0; t < 4; t++) {
            int rp = t * 32 + prow;
            float m = rm_s[rp], siv = ri_s[rp];
            float4 p;
            p.x = __uint_as_float(cvt_tf32(__expf(pe[t].x - m) * siv));
            p.y = __uint_as_float(cvt_tf32(__expf(pe[t].y - m) * siv));
            p.z = __uint_as_float(cvt_tf32(__expf(pe[t].z - m) * siv));
            p.w = __uint_as_float(cvt_tf32(__expf(pe[t].w - m) * siv));
            *(float4*)(P_ + rp * PPAD + pch * 4) = p;
            float4 h;
            h.x = __uint_as_float(cvt_tf32(be[t].x));
            h.y = __uint_as_float(cvt_tf32(be[t].y));
            h.z = __uint_as_float(cvt_tf32(be[t].z));
            h.w = __uint_as_float(cvt_tf32(be[t].w));
            *(float4*)(BH_ + (t * 8 + brow) * KNPAD + bch * 4) = h;
        }
        if (c + 1 < 64) {
            const int j0n = (c + 1) * 32;
            #pragma unroll
            for (int t = 0; t < 4; t++) {
                pe[t] = *(const float4*)(Eb + (size_t)(i0 + t * 32 + prow) * L_ + j0n + pch * 4);
                be[t] = *(const float4*)(Bb + (size_t)(j0n + t * 8 + brow) * D_ + d0 + bch * 4);
            }
        }
        __syncthreads();
        #pragma unroll
        for (int ks = 0; ks < 4; ks++) {
            const int kb = ks * 8;
            uint32_t pa[2][4], bh[8][2];
            #pragma unroll
            for (int mt = 0; mt < 2; mt++) {
                const int rb = wm * 32 + mt * 16;
                pa[mt][0] = __float_as_uint(P_[(rb + q) * PPAD + kb + r]);
                pa[mt][1] = __float_as_uint(P_[(rb + q + 8) * PPAD + kb + r]);
                pa[mt][2] = __float_as_uint(P_[(rb + q) * PPAD + kb + r + 4]);
                pa[mt][3] = __float_as_uint(P_[(rb + q + 8) * PPAD + kb + r + 4]);
            }
            #pragma unroll
            for (int nt = 0; nt < 8; nt++) {
                const int nb = wn * 64 + nt * 8;
                bh[nt][0] = __float_as_uint(BH_[(kb + r) * KNPAD + nb + q]);
                bh[nt][1] = __float_as_uint(BH_[(kb + r + 4) * KNPAD + nb + q]);
            }
            #pragma unroll
            for (int mt = 0; mt < 2; mt++)
                #pragma unroll
                for (int nt = 0; nt < 8; nt++)
                    mma8(acc[mt][nt], pa[mt], bh[nt]);
        }
        __syncthreads();
    }

    float* Ob = out + ((size_t)b * L_ + i0) * D_ + d0;
    #pragma unroll
    for (int mt = 0; mt < 2; mt++)
        #pragma unroll
        for (int nt = 0; nt < 8; nt++) {
            int row = wm * 32 + mt * 16 + q;
            int col = wn * 64 + nt * 8 + r * 2;
            *(float2*)(Ob + (size_t)row * D_ + col) =
                make_float2(acc[mt][nt][0], acc[mt][nt][1]);
            *(float2*)(Ob + (size_t)(row + 8) * D_ + col) =
                make_float2(acc[mt][nt][2], acc[mt][nt][3]);
        }
}

// ---------------------------------------------------------------------------
// b_tilda[j,d] = sum_i Q[i,j]*A[i,d].  Q tf32 (exp), A single tf32 (no lo).
// Qs [k=i][m=j] pad 136; AH [k=i][n=d] pad 136.
// ---------------------------------------------------------------------------
__global__ __launch_bounds__(256, 1) void k_btilda(const float* __restrict__ A,
                                                   float* __restrict__ out) {
    extern __shared__ float sm[];
    float* Qs = sm;                              // 2 * KNBUF
    float* AH = sm + 2 * KNBUF;                  // 2 * KNBUF
    float* cm_s = sm + 4 * KNBUF;
    float* ci_s = cm_s + 128;
    const int tid = threadIdx.x, lane = tid & 31, wid = tid >> 5;
    const int wm = wid & 3, wn = wid >> 2;
    const int q = lane >> 2, r = lane & 3;
    const int b = blockIdx.z, j0 = blockIdx.y * 128, d0 = blockIdx.x * 128;
    const float* Eb = g_E + (size_t)b * L_ * L_;
    const float* Ab = A + (size_t)b * L_ * D_;

    if (tid < 128) {
        cm_s[tid] = g_cmax[b * L_ + j0 + tid];
        ci_s[tid] = g_csumInv[b * L_ + j0 + tid];
    }

    float acc[2][8][4];
    #pragma unroll
    for (int mt = 0; mt < 2; mt++)
        #pragma unroll
        for (int nt = 0; nt < 8; nt++)
            #pragma unroll
            for (int e = 0; e < 4; e++) acc[mt][nt][e] = 0.f;

    const int srow = tid >> 5, sch = tid & 31;   // 8-row groups, 32 quads

    float4 qe[4], ae[4];
    #pragma unroll
    for (int t = 0; t < 4; t++) {
        int irow = t * 8 + srow;
        qe[t] = *(const float4*)(Eb + (size_t)irow * L_ + j0 + sch * 4);
        ae[t] = *(const float4*)(Ab + (size_t)irow * D_ + d0 + sch * 4);
    }
    __syncthreads();   // cm_s/ci_s visible

    for (int c = 0; c < 64; c++) {
        const int buf = c & 1;
        float* Q_ = Qs + buf * KNBUF;
        float* AH_ = AH + buf * KNBUF;
        #pragma unroll
        for (int t = 0; t < 4; t++) {
            int irow = t * 8 + srow;
            int jj = sch * 4;
            float4 p;
            p.x = __uint_as_float(cvt_tf32(__expf(qe[t].x - cm_s[jj]) * ci_s[jj]));
            p.y = __uint_as_float(cvt_tf32(__expf(qe[t].y - cm_s[jj + 1]) * ci_s[jj + 1]));
            p.z = __uint_as_float(cvt_tf32(__expf(qe[t].z - cm_s[jj + 2]) * ci_s[jj + 2]));
            p.w = __uint_as_float(cvt_tf32(__expf(qe[t].w - cm_s[jj + 3]) * ci_s[jj + 3]));
            *(float4*)(Q_ + irow * KNPAD + jj) = p;
            float4 h;
            h.x = __uint_as_float(cvt_tf32(ae[t].x));
            h.y = __uint_as_float(cvt_tf32(ae[t].y));
            h.z = __uint_as_float(cvt_tf32(ae[t].z));
            h.w = __uint_as_float(cvt_tf32(ae[t].w));
            *(float4*)(AH_ + irow * KNPAD + sch * 4) = h;
        }
        if (c + 1 < 64) {
            const int i0n = (c + 1) * 32;
            #pragma unroll
            for (int t = 0; t < 4; t++) {
                int irow = i0n + t * 8 + srow;
                qe[t] = *(const float4*)(Eb + (size_t)irow * L_ + j0 + sch * 4);
                ae[t] = *(const float4*)(Ab + (size_t)irow * D_ + d0 + sch * 4);
            }
        }
        __syncthreads();
        #pragma unroll
        for (int ks = 0; ks < 4; ks++) {
            const int kb = ks * 8;
            uint32_t qa[2][4], bh[8][2];
            #pragma unroll
            for (int mt = 0; mt < 2; mt++) {
                const int mb = wm * 32 + mt * 16;
                qa[mt][0] = __float_as_uint(Q_[(kb + r) * KNPAD + mb + q]);
                qa[mt][1] = __float_as_uint(Q_[(kb + r) * KNPAD + mb + q + 8]);
                qa[mt][2] = __float_as_uint(Q_[(kb + r + 4) * KNPAD + mb + q]);
                qa[mt][3] = __float_as_uint(Q_[(kb + r + 4) * KNPAD + mb + q + 8]);
            }
            #pragma unroll
            for (int nt = 0; nt < 8; nt++) {
                const int nb = wn * 64 + nt * 8;
                bh[nt][0] = __float_as_uint(AH_[(kb + r) * KNPAD + nb + q]);
                bh[nt][1] = __float_as_uint(AH_[(kb + r + 4) * KNPAD + nb + q]);
            }
            #pragma unroll
            for (int mt = 0; mt < 2; mt++)
                #pragma unroll
                for (int nt = 0; nt < 8; nt++)
                    mma8(acc[mt][nt], qa[mt], bh[nt]);
        }
        __syncthreads();
    }

    float* Ob = out + ((size_t)b * L_ + j0) * D_ + d0;
    #pragma unroll
    for (int mt = 0; mt < 2; mt++)
        #pragma unroll
        for (int nt = 0; nt < 8; nt++) {
            int row = wm * 32 + mt * 16 + q;
            int col = wn * 64 + nt * 8 + r * 2;
            *(float2*)(Ob + (size_t)row * D_ + col) =
                make_float2(acc[mt][nt][0], acc[mt][nt][1]);
            *(float2*)(Ob + (size_t)(row + 8) * D_ + col) =
                make_float2(acc[mt][nt][2], acc[mt][nt][3]);
        }
}

// ---------------------------------------------------------------------------
extern "C" void kernel_launch(void* const* d_in, const int* in_sizes, int n_in,
                              void* d_out, int out_size) {
    const float* A = (const float*)d_in[0];
    const float* B = (const float*)d_in[1];
    float* out = (float*)d_out;
    float* a_tilda = out;
    float* b_tilda = out + (size_t)BN_ * L_ * D_;

    const int SMEM_E = 8 * EBUF * 4;                            // 147456 B
    const int SMEM_A = (2 * PBUF + 2 * KNBUF + 256) * 4;        // 72704 B
    const int SMEM_B = (4 * KNBUF + 256) * 4;                   // 70656 B
    cudaFuncSetAttribute(k_gemm_e, cudaFuncAttributeMaxDynamicSharedMemorySize, SMEM_E);
    cudaFuncSetAttribute(k_atilda, cudaFuncAttributeMaxDynamicSharedMemorySize, SMEM_A);
    cudaFuncSetAttribute(k_btilda, cudaFuncAttributeMaxDynamicSharedMemorySize, SMEM_B);

    k_gemm_e<<<dim3(L_ / 128, L_ / 128, BN_), 256, SMEM_E>>>(A, B);
    k_rowstats<<<dim3(L_, BN_), 256>>>();
    k_colstats<<<dim3(L_ / 32, BN_), 256>>>();
    k_atilda<<<dim3(D_ / 128, L_ / 128, BN_), 256, SMEM_A>>>(B, a_tilda);
    k_btilda<<<dim3(D_ / 128, L_ / 128, BN_), 256, SMEM_B>>>(A, b_tilda);
}

// round 9
// speedup vs baseline: 1.5411x; 1.1798x over previous
#include <cuda_runtime.h>
#include <math.h>
#include <stdint.h>

#define BN_ 8
#define L_ 2048
#define D_ 1024

// Scratch
__device__ float g_E[(size_t)BN_ * L_ * L_];
__device__ float g_rmax[BN_ * L_];
__device__ float g_rsumInv[BN_ * L_];
__device__ float g_cmax[BN_ * L_];
__device__ float g_csumInv[BN_ * L_];

#define NEG_INF __int_as_float(0xff800000)

static __device__ __forceinline__ uint32_t cvt_tf32(float x) {
    uint32_t h;
    asm("cvt.rna.tf32.f32 %0, %1;" : "=r"(h) : "f"(x));
    return h;
}
// pack two floats to bf16x2: lo half = lo arg, hi half = hi arg
static __device__ __forceinline__ uint32_t bf2(float lo, float hi) {
    uint32_t d;
    asm("cvt.rn.bf16x2.f32 %0, %1, %2;" : "=r"(d) : "f"(hi), "f"(lo));
    return d;
}
static __device__ __forceinline__ float bflo(uint32_t p) { return __uint_as_float(p << 16); }
static __device__ __forceinline__ float bfhi(uint32_t p) { return __uint_as_float(p & 0xffff0000u); }

// tf32 m16n8k8
static __device__ __forceinline__ void mma8(float c[4], const uint32_t a[4],
                                            const uint32_t b[2]) {
    asm volatile(
        "mma.sync.aligned.m16n8k8.row.col.f32.tf32.tf32.f32 "
        "{%0,%1,%2,%3},{%4,%5,%6,%7},{%8,%9},{%0,%1,%2,%3};"
        : "+f"(c[0]), "+f"(c[1]), "+f"(c[2]), "+f"(c[3])
        : "r"(a[0]), "r"(a[1]), "r"(a[2]), "r"(a[3]), "r"(b[0]), "r"(b[1]));
}
// bf16 m16n8k16
static __device__ __forceinline__ void mma16(float c[4], const uint32_t a[4],
                                             const uint32_t b[2]) {
    asm volatile(
        "mma.sync.aligned.m16n8k16.row.col.f32.bf16.bf16.f32 "
        "{%0,%1,%2,%3},{%4,%5,%6,%7},{%8,%9},{%0,%1,%2,%3};"
        : "+f"(c[0]), "+f"(c[1]), "+f"(c[2]), "+f"(c[3])
        : "r"(a[0]), "r"(a[1]), "r"(a[2]), "r"(a[3]), "r"(b[0]), "r"(b[1]));
}

// ---------------------------------------------------------------------------
// E = A @ B^T via 3xBF16 (hh + hl + lh), m16n8k16. 128x128 tile, BK=32,
// 8 warps (4m x 2n), 256 thr.  SMEM: packed bf16x2 [row][k-pair] u32, pad 20.
// ---------------------------------------------------------------------------
#define EP2 20
#define EB2 (128 * EP2)
__global__ __launch_bounds__(256, 1) void k_gemm_e(const float* __restrict__ A,
                                                   const float* __restrict__ B) {
    extern __shared__ uint32_t smu[];
    uint32_t* tAH = smu;                 // 2 * EB2
    uint32_t* tAL = smu + 2 * EB2;
    uint32_t* tBH = smu + 4 * EB2;
    uint32_t* tBL = smu + 6 * EB2;
    const int tid = threadIdx.x, lane = tid & 31, wid = tid >> 5;
    const int wm = wid & 3, wn = wid >> 2;
    const int q = lane >> 2, r = lane & 3;
    const int b = blockIdx.z, i0 = blockIdx.y * 128, j0 = blockIdx.x * 128;
    const float* Ab = A + ((size_t)b * L_ + i0) * D_;
    const float* Bb = B + ((size_t)b * L_ + j0) * D_;

    float acc[2][8][4];
    #pragma unroll
    for (int mt = 0; mt < 2; mt++)
        #pragma unroll
        for (int nt = 0; nt < 8; nt++)
            #pragma unroll
            for (int e = 0; e < 4; e++) acc[mt][nt][e] = 0.f;

    const int srow = tid >> 2;        // 0..63 (row within 64-row half)
    const int sc4 = tid & 3;          // 8-float group 0..3

    float4 av[2][2], bv[2][2];
    #define LOADREGS_E(c)                                                              \
        do {                                                                           \
            const int _k0 = (c) * 32 + sc4 * 8;                                        \
            _Pragma("unroll")                                                          \
            for (int t = 0; t < 2; t++) {                                              \
                int row = t * 64 + srow;                                               \
                av[t][0] = *(const float4*)(Ab + (size_t)row * D_ + _k0);              \
                av[t][1] = *(const float4*)(Ab + (size_t)row * D_ + _k0 + 4);          \
                bv[t][0] = *(const float4*)(Bb + (size_t)row * D_ + _k0);              \
                bv[t][1] = *(const float4*)(Bb + (size_t)row * D_ + _k0 + 4);          \
            }                                                                          \
        } while (0)
    // split+pack one float4 pair -> 4 h-words and 4 l-words, store as uint4
    #define PACKSTORE(dstH, dstL, v0, v1, off)                                          \
        do {                                                                            \
            uint32_t h0 = bf2((v0).x, (v0).y), h1 = bf2((v0).z, (v0).w);                \
            uint32_t h2 = bf2((v1).x, (v1).y), h3 = bf2((v1).z, (v1).w);                \
            uint32_t l0 = bf2((v0).x - bflo(h0), (v0).y - bfhi(h0));                    \
            uint32_t l1 = bf2((v0).z - bflo(h1), (v0).w - bfhi(h1));                    \
            uint32_t l2 = bf2((v1).x - bflo(h2), (v1).y - bfhi(h2));                    \
            uint32_t l3 = bf2((v1).z - bflo(h3), (v1).w - bfhi(h3));                    \
            *(uint4*)((dstH) + (off)) = make_uint4(h0, h1, h2, h3);                     \
            *(uint4*)((dstL) + (off)) = make_uint4(l0, l1, l2, l3);                     \
        } while (0)
    #define STAGE_E(bufn)                                                              \
        do {                                                                           \
            _Pragma("unroll")                                                          \
            for (int t = 0; t < 2; t++) {                                              \
                int row = t * 64 + srow;                                               \
                int off = (bufn) * EB2 + row * EP2 + sc4 * 4;                          \
                PACKSTORE(tAH, tAL, av[t][0], av[t][1], off);                          \
                PACKSTORE(tBH, tBL, bv[t][0], bv[t][1], off);                          \
            }                                                                          \
        } while (0)

    LOADREGS_E(0);
    for (int c = 0; c < 32; c++) {
        const int buf = c & 1;
        STAGE_E(buf);
        if (c + 1 < 32) LOADREGS_E(c + 1);
        __syncthreads();
        const uint32_t* AH_ = tAH + buf * EB2;
        const uint32_t* AL_ = tAL + buf * EB2;
        const uint32_t* BH_ = tBH + buf * EB2;
        const uint32_t* BL_ = tBL + buf * EB2;
        #pragma unroll
        for (int ks = 0; ks < 2; ks++) {
            const int kb2 = ks * 8;
            uint32_t ah[2][4], al[2][4], bh[8][2], bl[8][2];
            #pragma unroll
            for (int mt = 0; mt < 2; mt++) {
                const int rb = wm * 32 + mt * 16;
                ah[mt][0] = AH_[(rb + q) * EP2 + kb2 + r];
                ah[mt][1] = AH_[(rb + q + 8) * EP2 + kb2 + r];
                ah[mt][2] = AH_[(rb + q) * EP2 + kb2 + r + 4];
                ah[mt][3] = AH_[(rb + q + 8) * EP2 + kb2 + r + 4];
                al[mt][0] = AL_[(rb + q) * EP2 + kb2 + r];
                al[mt][1] = AL_[(rb + q + 8) * EP2 + kb2 + r];
                al[mt][2] = AL_[(rb + q) * EP2 + kb2 + r + 4];
                al[mt][3] = AL_[(rb + q + 8) * EP2 + kb2 + r + 4];
            }
            #pragma unroll
            for (int nt = 0; nt < 8; nt++) {
                const int nb = wn * 64 + nt * 8;
                bh[nt][0] = BH_[(nb + q) * EP2 + kb2 + r];
                bh[nt][1] = BH_[(nb + q) * EP2 + kb2 + r + 4];
                bl[nt][0] = BL_[(nb + q) * EP2 + kb2 + r];
                bl[nt][1] = BL_[(nb + q) * EP2 + kb2 + r + 4];
            }
            #pragma unroll
            for (int mt = 0; mt < 2; mt++)
                #pragma unroll
                for (int nt = 0; nt < 8; nt++) {
                    mma16(acc[mt][nt], al[mt], bh[nt]);
                    mma16(acc[mt][nt], ah[mt], bl[nt]);
                    mma16(acc[mt][nt], ah[mt], bh[nt]);
                }
        }
        __syncthreads();
    }
    #undef STAGE_E
    #undef PACKSTORE
    #undef LOADREGS_E

    float* Eb = g_E + ((size_t)b * L_ + i0) * L_ + j0;
    #pragma unroll
    for (int mt = 0; mt < 2; mt++)
        #pragma unroll
        for (int nt = 0; nt < 8; nt++) {
            int row = wm * 32 + mt * 16 + q;
            int col = wn * 64 + nt * 8 + r * 2;
            *(float2*)(Eb + (size_t)row * L_ + col) =
                make_float2(acc[mt][nt][0], acc[mt][nt][1]);
            *(float2*)(Eb + (size_t)(row + 8) * L_ + col) =
                make_float2(acc[mt][nt][2], acc[mt][nt][3]);
        }
}

// ---------------------------------------------------------------------------
// Row / col softmax stats
// ---------------------------------------------------------------------------
__global__ __launch_bounds__(256) void k_rowstats() {
    const int b = blockIdx.y, rrow = blockIdx.x;
    const float* row = g_E + (size_t)(b * L_ + rrow) * L_;
    const int tid = threadIdx.x;
    __shared__ float red[256];

    float m = NEG_INF;
    for (int j = tid * 4; j < L_; j += 1024) {
        float4 v = *(const float4*)(row + j);
        m = fmaxf(m, fmaxf(fmaxf(v.x, v.y), fmaxf(v.z, v.w)));
    }
    red[tid] = m; __syncthreads();
    for (int s = 128; s >= 1; s >>= 1) {
        if (tid < s) red[tid] = fmaxf(red[tid], red[tid + s]);
        __syncthreads();
    }
    const float M = red[0];
    __syncthreads();

    float sum = 0.f;
    for (int j = tid * 4; j < L_; j += 1024) {
        float4 v = *(const float4*)(row + j);
        sum += __expf(v.x - M) + __expf(v.y - M) + __expf(v.z - M) + __expf(v.w - M);
    }
    red[tid] = sum; __syncthreads();
    for (int s = 128; s >= 1; s >>= 1) {
        if (tid < s) red[tid] += red[tid + s];
        __syncthreads();
    }
    if (tid == 0) {
        g_rmax[b * L_ + rrow] = M;
        g_rsumInv[b * L_ + rrow] = 1.0f / red[0];
    }
}

__global__ __launch_bounds__(256) void k_colstats() {
    const int b = blockIdx.y;
    const int jt = threadIdx.x & 31;
    const int isl = threadIdx.x >> 5;
    const int j = blockIdx.x * 32 + jt;
    const float* base = g_E + (size_t)b * L_ * L_ + j;

    float m = NEG_INF, s = 0.f;
    const int ibeg = isl * 256, iend = ibeg + 256;
    for (int i = ibeg; i < iend; i++) {
        float x = base[(size_t)i * L_];
        if (x <= m) {
            s += __expf(x - m);
        } else {
            s = s * __expf(m - x) + 1.f;
            m = x;
        }
    }
    __shared__ float ms[8][32], ss[8][32];
    ms[isl][jt] = m; ss[isl][jt] = s;
    __syncthreads();
    if (isl == 0) {
        float M = m, S = s;
        #pragma unroll
        for (int k = 1; k < 8; k++) {
            float mk = ms[k][jt], sk = ss[k][jt];
            if (mk <= M) {
                S += sk * __expf(mk - M);
            } else {
                S = S * __expf(M - mk) + sk;
                M = mk;
            }
        }
        g_cmax[b * L_ + j] = M;
        g_csumInv[b * L_ + j] = 1.0f / S;
    }
}

// ---------------------------------------------------------------------------
// a_tilda[i,d] = sum_j P[i,j]*B[j,d].  P tf32 (exp), B single tf32 (no lo).
// Ps [m=i][k=j] pad 36; BH [k=j][n=d] pad 136.  8 warps (4m x 2n), 256 thr.
// ---------------------------------------------------------------------------
#define PPAD 36
#define PBUF (128 * PPAD)
#define KNPAD 136
#define KNBUF (32 * KNPAD)
__global__ __launch_bounds__(256, 1) void k_atilda(const float* __restrict__ B,
                                                   float* __restrict__ out) {
    extern __shared__ float sm[];
    float* Ps = sm;                              // 2 * PBUF
    float* BH = sm + 2 * PBUF;                   // 2 * KNBUF
    float* rm_s = sm + 2 * PBUF + 2 * KNBUF;
    float* ri_s = rm_s + 128;
    const int tid = threadIdx.x, lane = tid & 31, wid = tid >> 5;
    const int wm = wid & 3, wn = wid >> 2;
    const int q = lane >> 2, r = lane & 3;
    const int b = blockIdx.z, i0 = blockIdx.y * 128, d0 = blockIdx.x * 128;
    const float* Eb = g_E + (size_t)b * L_ * L_;
    const float* Bb = B + (size_t)b * L_ * D_;

    if (tid < 128) {
        rm_s[tid] = g_rmax[b * L_ + i0 + tid];
        ri_s[tid] = g_rsumInv[b * L_ + i0 + tid];
    }

    float acc[2][8][4];
    #pragma unroll
    for (int mt = 0; mt < 2; mt++)
        #pragma unroll
        for (int nt = 0; nt < 8; nt++)
            #pragma unroll
            for (int e = 0; e < 4; e++) acc[mt][nt][e] = 0.f;

    const int prow = tid >> 3, pch = tid & 7;        // P: 32-row groups
    const int brow = tid >> 5, bch = tid & 31;       // B: 8-row groups

    float4 pe[4], be[4];
    #pragma unroll
    for (int t = 0; t < 4; t++) {
        pe[t] = *(const float4*)(Eb + (size_t)(i0 + t * 32 + prow) * L_ + pch * 4);
        be[t] = *(const float4*)(Bb + (size_t)(t * 8 + brow) * D_ + d0 + bch * 4);
    }
    __syncthreads();   // rm_s/ri_s visible

    for (int c = 0; c < 64; c++) {
        const int buf = c & 1;
        float* P_ = Ps + buf * PBUF;
        float* BH_ = BH + buf * KNBUF;
        #pragma unroll
        for (int t = 0; t < 4; t++) {
            int rp = t * 32 + prow;
            float m = rm_s[rp], siv = ri_s[rp];
            float4 p;
            p.x = __uint_as_float(cvt_tf32(__expf(pe[t].x - m) * siv));
            p.y = __uint_as_float(cvt_tf32(__expf(pe[t].y - m) * siv));
            p.z = __uint_as_float(cvt_tf32(__expf(pe[t].z - m) * siv));
            p.w = __uint_as_float(cvt_tf32(__expf(pe[t].w - m) * siv));
            *(float4*)(P_ + rp * PPAD + pch * 4) = p;
            float4 h;
            h.x = __uint_as_float(cvt_tf32(be[t].x));
            h.y = __uint_as_float(cvt_tf32(be[t].y));
            h.z = __uint_as_float(cvt_tf32(be[t].z));
            h.w = __uint_as_float(cvt_tf32(be[t].w));
            *(float4*)(BH_ + (t * 8 + brow) * KNPAD + bch * 4) = h;
        }
        if (c + 1 < 64) {
            const int j0n = (c + 1) * 32;
            #pragma unroll
            for (int t = 0; t < 4; t++) {
                pe[t] = *(const float4*)(Eb + (size_t)(i0 + t * 32 + prow) * L_ + j0n + pch * 4);
                be[t] = *(const float4*)(Bb + (size_t)(j0n + t * 8 + brow) * D_ + d0 + bch * 4);
            }
        }
        __syncthreads();
        #pragma unroll
        for (int ks = 0; ks < 4; ks++) {
            const int kb = ks * 8;
            uint32_t pa[2][4], bh[8][2];
            #pragma unroll
            for (int mt = 0; mt < 2; mt++) {
                const int rb = wm * 32 + mt * 16;
                pa[mt][0] = __float_as_uint(P_[(rb + q) * PPAD + kb + r]);
                pa[mt][1] = __float_as_uint(P_[(rb + q + 8) * PPAD + kb + r]);
                pa[mt][2] = __float_as_uint(P_[(rb + q) * PPAD + kb + r + 4]);
                pa[mt][3] = __float_as_uint(P_[(rb + q + 8) * PPAD + kb + r + 4]);
            }
            #pragma unroll
            for (int nt = 0; nt < 8; nt++) {
                const int nb = wn * 64 + nt * 8;
                bh[nt][0] = __float_as_uint(BH_[(kb + r) * KNPAD + nb + q]);
                bh[nt][1] = __float_as_uint(BH_[(kb + r + 4) * KNPAD + nb + q]);
            }
            #pragma unroll
            for (int mt = 0; mt < 2; mt++)
                #pragma unroll
                for (int nt = 0; nt < 8; nt++)
                    mma8(acc[mt][nt], pa[mt], bh[nt]);
        }
        __syncthreads();
    }

    float* Ob = out + ((size_t)b * L_ + i0) * D_ + d0;
    #pragma unroll
    for (int mt = 0; mt < 2; mt++)
        #pragma unroll
        for (int nt = 0; nt < 8; nt++) {
            int row = wm * 32 + mt * 16 + q;
            int col = wn * 64 + nt * 8 + r * 2;
            *(float2*)(Ob + (size_t)row * D_ + col) =
                make_float2(acc[mt][nt][0], acc[mt][nt][1]);
            *(float2*)(Ob + (size_t)(row + 8) * D_ + col) =
                make_float2(acc[mt][nt][2], acc[mt][nt][3]);
        }
}

// ---------------------------------------------------------------------------
// b_tilda[j,d] = sum_i Q[i,j]*A[i,d].  Q tf32 (exp), A single tf32 (no lo).
// Qs [k=i][m=j] pad 136; AH [k=i][n=d] pad 136.
// ---------------------------------------------------------------------------
__global__ __launch_bounds__(256, 1) void k_btilda(const float* __restrict__ A,
                                                   float* __restrict__ out) {
    extern __shared__ float sm[];
    float* Qs = sm;                              // 2 * KNBUF
    float* AH = sm + 2 * KNBUF;                  // 2 * KNBUF
    float* cm_s = sm + 4 * KNBUF;
    float* ci_s = cm_s + 128;
    const int tid = threadIdx.x, lane = tid & 31, wid = tid >> 5;
    const int wm = wid & 3, wn = wid >> 2;
    const int q = lane >> 2, r = lane & 3;
    const int b = blockIdx.z, j0 = blockIdx.y * 128, d0 = blockIdx.x * 128;
    const float* Eb = g_E + (size_t)b * L_ * L_;
    const float* Ab = A + (size_t)b * L_ * D_;

    if (tid < 128) {
        cm_s[tid] = g_cmax[b * L_ + j0 + tid];
        ci_s[tid] = g_csumInv[b * L_ + j0 + tid];
    }

    float acc[2][8][4];
    #pragma unroll
    for (int mt = 0; mt < 2; mt++)
        #pragma unroll
        for (int nt = 0; nt < 8; nt++)
            #pragma unroll
            for (int e = 0; e < 4; e++) acc[mt][nt][e] = 0.f;

    const int srow = tid >> 5, sch = tid & 31;   // 8-row groups, 32 quads

    float4 qe[4], ae[4];
    #pragma unroll
    for (int t = 0; t < 4; t++) {
        int irow = t * 8 + srow;
        qe[t] = *(const float4*)(Eb + (size_t)irow * L_ + j0 + sch * 4);
        ae[t] = *(const float4*)(Ab + (size_t)irow * D_ + d0 + sch * 4);
    }
    __syncthreads();   // cm_s/ci_s visible

    for (int c = 0; c < 64; c++) {
        const int buf = c & 1;
        float* Q_ = Qs + buf * KNBUF;
        float* AH_ = AH + buf * KNBUF;
        #pragma unroll
        for (int t = 0; t < 4; t++) {
            int irow = t * 8 + srow;
            int jj = sch * 4;
            float4 p;
            p.x = __uint_as_float(cvt_tf32(__expf(qe[t].x - cm_s[jj]) * ci_s[jj]));
            p.y = __uint_as_float(cvt_tf32(__expf(qe[t].y - cm_s[jj + 1]) * ci_s[jj + 1]));
            p.z = __uint_as_float(cvt_tf32(__expf(qe[t].z - cm_s[jj + 2]) * ci_s[jj + 2]));
            p.w = __uint_as_float(cvt_tf32(__expf(qe[t].w - cm_s[jj + 3]) * ci_s[jj + 3]));
            *(float4*)(Q_ + irow * KNPAD + jj) = p;
            float4 h;
            h.x = __uint_as_float(cvt_tf32(ae[t].x));
            h.y = __uint_as_float(cvt_tf32(ae[t].y));
            h.z = __uint_as_float(cvt_tf32(ae[t].z));
            h.w = __uint_as_float(cvt_tf32(ae[t].w));
            *(float4*)(AH_ + irow * KNPAD + sch * 4) = h;
        }
        if (c + 1 < 64) {
            const int i0n = (c + 1) * 32;
            #pragma unroll
            for (int t = 0; t < 4; t++) {
                int irow = i0n + t * 8 + srow;
                qe[t] = *(const float4*)(Eb + (size_t)irow * L_ + j0 + sch * 4);
                ae[t] = *(const float4*)(Ab + (size_t)irow * D_ + d0 + sch * 4);
            }
        }
        __syncthreads();
        #pragma unroll
        for (int ks = 0; ks < 4; ks++) {
            const int kb = ks * 8;
            uint32_t qa[2][4], bh[8][2];
            #pragma unroll
            for (int mt = 0; mt < 2; mt++) {
                const int mb = wm * 32 + mt * 16;
                qa[mt][0] = __float_as_uint(Q_[(kb + r) * KNPAD + mb + q]);
                qa[mt][1] = __float_as_uint(Q_[(kb + r) * KNPAD + mb + q + 8]);
                qa[mt][2] = __float_as_uint(Q_[(kb + r + 4) * KNPAD + mb + q]);
                qa[mt][3] = __float_as_uint(Q_[(kb + r + 4) * KNPAD + mb + q + 8]);
            }
            #pragma unroll
            for (int nt = 0; nt < 8; nt++) {
                const int nb = wn * 64 + nt * 8;
                bh[nt][0] = __float_as_uint(AH_[(kb + r) * KNPAD + nb + q]);
                bh[nt][1] = __float_as_uint(AH_[(kb + r + 4) * KNPAD + nb + q]);
            }
            #pragma unroll
            for (int mt = 0; mt < 2; mt++)
                #pragma unroll
                for (int nt = 0; nt < 8; nt++)
                    mma8(acc[mt][nt], qa[mt], bh[nt]);
        }
        __syncthreads();
    }

    float* Ob = out + ((size_t)b * L_ + j0) * D_ + d0;
    #pragma unroll
    for (int mt = 0; mt < 2; mt++)
        #pragma unroll
        for (int nt = 0; nt < 8; nt++) {
            int row = wm * 32 + mt * 16 + q;
            int col = wn * 64 + nt * 8 + r * 2;
            *(float2*)(Ob + (size_t)row * D_ + col) =
                make_float2(acc[mt][nt][0], acc[mt][nt][1]);
            *(float2*)(Ob + (size_t)(row + 8) * D_ + col) =
                make_float2(acc[mt][nt][2], acc[mt][nt][3]);
        }
}

// ---------------------------------------------------------------------------
extern "C" void kernel_launch(void* const* d_in, const int* in_sizes, int n_in,
                              void* d_out, int out_size) {
    const float* A = (const float*)d_in[0];
    const float* B = (const float*)d_in[1];
    float* out = (float*)d_out;
    float* a_tilda = out;
    float* b_tilda = out + (size_t)BN_ * L_ * D_;

    const int SMEM_E = 8 * EB2 * 4;                             // 81920 B
    const int SMEM_A = (2 * PBUF + 2 * KNBUF + 256) * 4;        // 72704 B
    const int SMEM_B = (4 * KNBUF + 256) * 4;                   // 70656 B
    cudaFuncSetAttribute(k_gemm_e, cudaFuncAttributeMaxDynamicSharedMemorySize, SMEM_E);
    cudaFuncSetAttribute(k_atilda, cudaFuncAttributeMaxDynamicSharedMemorySize, SMEM_A);
    cudaFuncSetAttribute(k_btilda, cudaFuncAttributeMaxDynamicSharedMemorySize, SMEM_B);

    k_gemm_e<<<dim3(L_ / 128, L_ / 128, BN_), 256, SMEM_E>>>(A, B);
    k_rowstats<<<dim3(L_, BN_), 256>>>();
    k_colstats<<<dim3(L_ / 32, BN_), 256>>>();
    k_atilda<<<dim3(D_ / 128, L_ / 128, BN_), 256, SMEM_A>>>(B, a_tilda);
    k_btilda<<<dim3(D_ / 128, L_ / 128, BN_), 256, SMEM_B>>>(A, b_tilda);
}